// round 4
// baseline (speedup 1.0000x reference)
#include <cuda_runtime.h>
#include <math_constants.h>
#include <cstddef>

// Problem constants
#define BSZ 4
#define SEQ 2048
#define DIM 1024          // D = KD = VD = 1024
#define MTOT (BSZ * SEQ)  // 8192

// Scratch (allocation-free: __device__ globals)
__device__ float g_q[(size_t)MTOT * DIM];          // 32 MB
__device__ float g_k[(size_t)MTOT * DIM];          // 32 MB
__device__ float g_v[(size_t)MTOT * DIM];          // 32 MB
__device__ float g_p[(size_t)BSZ * SEQ * SEQ];     // 64 MB
__device__ float g_o[(size_t)MTOT * DIM];          // 32 MB

// ---------------------------------------------------------------------------
// Tiled SGEMM: 128x128 block tile, BK=16, 256 threads, 8x8 microtile.
// MODE 0: C = A(MxK, row-major) * B(NxK, row-major)^T + bias[n]      (NT+bias)
// MODE 1: C = |A*B^T| * (1/32) with causal mask (c<=r else -inf)     (scores)
// MODE 2: C = A(MxK) * B(KxN, row-major), k-loop limited to row tile (PV)
// blockIdx.z = batch, with element strides sA/sB/sC.
// All dims are multiples of the tile sizes for this problem (no bounds checks).
// ---------------------------------------------------------------------------
#define BM 128
#define BN 128
#define BK 16
#define TM 8
#define TN 8

template <int MODE>
__global__ void __launch_bounds__(256, 2)
gemm_kernel(const float* __restrict__ A, const float* __restrict__ Bm,
            const float* __restrict__ bias, float* __restrict__ C,
            int K, int lda, int ldb, int ldc,
            size_t sA, size_t sB, size_t sC)
{
    const int bz = blockIdx.z;
    A  += (size_t)bz * sA;
    Bm += (size_t)bz * sB;
    C  += (size_t)bz * sC;

    const int rowStart = blockIdx.y * BM;
    const int colStart = blockIdx.x * BN;
    const int tid = threadIdx.x;
    const int tx = tid & 15;       // 0..15
    const int ty = tid >> 4;       // 0..15

    // Fully-masked score tile: strict upper triangle of tile grid
    if (MODE == 1 && colStart > rowStart + BM - 1) {
        #pragma unroll
        for (int i = 0; i < TM; i++) {
            const size_t r = (size_t)(rowStart + ty * TM + i);
            float4 ninf = make_float4(-CUDART_INF_F, -CUDART_INF_F,
                                      -CUDART_INF_F, -CUDART_INF_F);
            float4* dst = reinterpret_cast<float4*>(&C[r * ldc + colStart + tx * TN]);
            dst[0] = ninf;
            dst[1] = ninf;
        }
        return;
    }

    __shared__ float As[BK][BM];
    __shared__ float Bs[BK][BN];

    float acc[TM][TN] = {};

    int kEnd = K;
    if (MODE == 2) kEnd = min(K, rowStart + BM);   // causal: P[r, k>r] == 0

    for (int k0 = 0; k0 < kEnd; k0 += BK) {
        // --- load A tile (BM x BK), transpose into As[k][m] ---
        #pragma unroll
        for (int l = 0; l < 2; l++) {
            const int idx = tid + l * 256;         // 0..511
            const int m  = idx >> 2;               // 4 float4 per row
            const int c4 = (idx & 3) * 4;
            const float4 v = *reinterpret_cast<const float4*>(
                &A[(size_t)(rowStart + m) * lda + k0 + c4]);
            As[c4 + 0][m] = v.x;
            As[c4 + 1][m] = v.y;
            As[c4 + 2][m] = v.z;
            As[c4 + 3][m] = v.w;
        }
        // --- load B tile ---
        if (MODE != 2) {
            // B is N x K row-major (NT): transpose into Bs[k][n]
            #pragma unroll
            for (int l = 0; l < 2; l++) {
                const int idx = tid + l * 256;
                const int n  = idx >> 2;
                const int c4 = (idx & 3) * 4;
                const float4 v = *reinterpret_cast<const float4*>(
                    &Bm[(size_t)(colStart + n) * ldb + k0 + c4]);
                Bs[c4 + 0][n] = v.x;
                Bs[c4 + 1][n] = v.y;
                Bs[c4 + 2][n] = v.z;
                Bs[c4 + 3][n] = v.w;
            }
        } else {
            // B is K x N row-major (NN): direct copy rows into Bs[k][n]
            #pragma unroll
            for (int l = 0; l < 2; l++) {
                const int idx = tid + l * 256;
                const int kk = idx >> 5;           // 32 float4 per 128-col row
                const int c4 = (idx & 31) * 4;
                const float4 v = *reinterpret_cast<const float4*>(
                    &Bm[(size_t)(k0 + kk) * ldb + colStart + c4]);
                *reinterpret_cast<float4*>(&Bs[kk][c4]) = v;
            }
        }
        __syncthreads();

        #pragma unroll
        for (int kk = 0; kk < BK; kk++) {
            float ar[TM], br[TN];
            #pragma unroll
            for (int i = 0; i < TM; i++) ar[i] = As[kk][ty * TM + i];
            #pragma unroll
            for (int j = 0; j < TN; j++) br[j] = Bs[kk][tx * TN + j];
            #pragma unroll
            for (int i = 0; i < TM; i++)
                #pragma unroll
                for (int j = 0; j < TN; j++)
                    acc[i][j] = fmaf(ar[i], br[j], acc[i][j]);
        }
        __syncthreads();
    }

    // --- epilogue ---
    if (MODE == 0) {
        #pragma unroll
        for (int i = 0; i < TM; i++) {
            const size_t r = (size_t)(rowStart + ty * TM + i);
            #pragma unroll
            for (int j = 0; j < TN; j++) {
                const int c = colStart + tx * TN + j;
                C[r * ldc + c] = acc[i][j] + bias[c];
            }
        }
    } else if (MODE == 1) {
        const float scale = 0.03125f;  // 1/sqrt(1024)
        const int r0 = rowStart + ty * TM;
        #pragma unroll
        for (int i = 0; i < TM; i++) {
            const int r = r0 + i;
            #pragma unroll
            for (int j = 0; j < TN; j++) {
                const int c = colStart + tx * TN + j;
                C[(size_t)r * ldc + c] =
                    (c <= r) ? fabsf(acc[i][j]) * scale : -CUDART_INF_F;
            }
        }
    } else {
        #pragma unroll
        for (int i = 0; i < TM; i++) {
            const size_t r = (size_t)(rowStart + ty * TM + i);
            #pragma unroll
            for (int j = 0; j < TN; j++)
                C[r * ldc + colStart + tx * TN + j] = acc[i][j];
        }
    }
}

// ---------------------------------------------------------------------------
// Row softmax over SEQ=2048 entries; one 256-thread block per row.
// -inf entries (causal mask) become exactly 0.
// ---------------------------------------------------------------------------
__global__ void __launch_bounds__(256)
softmax_kernel(float* __restrict__ P)
{
    const size_t row = blockIdx.x;
    float* p = P + row * SEQ;
    const int tid = threadIdx.x;

    __shared__ float red[8];

    float vals[8];
    float m = -CUDART_INF_F;
    #pragma unroll
    for (int i = 0; i < 8; i++) {
        vals[i] = p[tid + i * 256];
        m = fmaxf(m, vals[i]);
    }
    #pragma unroll
    for (int o = 16; o; o >>= 1) m = fmaxf(m, __shfl_xor_sync(0xffffffffu, m, o));
    if ((tid & 31) == 0) red[tid >> 5] = m;
    __syncthreads();
    if (tid == 0) {
        float t = red[0];
        #pragma unroll
        for (int w = 1; w < 8; w++) t = fmaxf(t, red[w]);
        red[0] = t;
    }
    __syncthreads();
    m = red[0];
    __syncthreads();

    float s = 0.0f;
    #pragma unroll
    for (int i = 0; i < 8; i++) {
        vals[i] = __expf(vals[i] - m);   // exp(-inf - m) == 0
        s += vals[i];
    }
    #pragma unroll
    for (int o = 16; o; o >>= 1) s += __shfl_xor_sync(0xffffffffu, s, o);
    if ((tid & 31) == 0) red[tid >> 5] = s;
    __syncthreads();
    if (tid == 0) {
        float t = 0.0f;
        #pragma unroll
        for (int w = 0; w < 8; w++) t += red[w];
        red[0] = t;
    }
    __syncthreads();
    const float inv = 1.0f / red[0];

    #pragma unroll
    for (int i = 0; i < 8; i++)
        p[tid + i * 256] = vals[i] * inv;
}

// ---------------------------------------------------------------------------
extern "C" void kernel_launch(void* const* d_in, const int* in_sizes, int n_in,
                              void* d_out, int out_size)
{
    const float* x  = (const float*)d_in[0];
    const float* Wq = (const float*)d_in[1];
    const float* bq = (const float*)d_in[2];
    const float* Wk = (const float*)d_in[3];
    const float* bk = (const float*)d_in[4];
    const float* Wv = (const float*)d_in[5];
    const float* bv = (const float*)d_in[6];
    const float* Wo = (const float*)d_in[7];
    const float* bo = (const float*)d_in[8];
    float* out = (float*)d_out;

    float *q, *k, *v, *p, *o;
    cudaGetSymbolAddress((void**)&q, g_q);
    cudaGetSymbolAddress((void**)&k, g_k);
    cudaGetSymbolAddress((void**)&v, g_v);
    cudaGetSymbolAddress((void**)&p, g_p);
    cudaGetSymbolAddress((void**)&o, g_o);

    // 1. Q/K/V projections: C[8192,1024] = x * W^T + b   (NT)
    {
        dim3 grid(DIM / BN, MTOT / BM, 1);
        gemm_kernel<0><<<grid, 256>>>(x, Wq, bq, q, DIM, DIM, DIM, DIM, 0, 0, 0);
        gemm_kernel<0><<<grid, 256>>>(x, Wk, bk, k, DIM, DIM, DIM, DIM, 0, 0, 0);
        gemm_kernel<0><<<grid, 256>>>(x, Wv, bv, v, DIM, DIM, DIM, DIM, 0, 0, 0);
    }

    // 2. scores: P[b] = causal(|Q K^T| / 32), per batch   (NT, MODE 1)
    {
        dim3 grid(SEQ / BN, SEQ / BM, BSZ);
        gemm_kernel<1><<<grid, 256>>>(q, k, nullptr, p,
                                      DIM, DIM, DIM, SEQ,
                                      (size_t)SEQ * DIM, (size_t)SEQ * DIM,
                                      (size_t)SEQ * SEQ);
    }

    // 3. row softmax over keys
    softmax_kernel<<<BSZ * SEQ, 256>>>(p);

    // 4. O[b] = P[b] * V[b]   (NN, MODE 2, causal k-limit)
    {
        dim3 grid(DIM / BN, SEQ / BM, BSZ);
        gemm_kernel<2><<<grid, 256>>>(p, v, nullptr, o,
                                      SEQ, SEQ, DIM, DIM,
                                      (size_t)SEQ * SEQ, (size_t)SEQ * DIM,
                                      (size_t)SEQ * DIM);
    }

    // 5. output projection: out = O * Wo^T + bo   (NT)
    {
        dim3 grid(DIM / BN, MTOT / BM, 1);
        gemm_kernel<0><<<grid, 256>>>(o, Wo, bo, out, DIM, DIM, DIM, DIM, 0, 0, 0);
    }
}

// round 13
// speedup vs baseline: 2.0552x; 2.0552x over previous
#include <cuda_runtime.h>
#include <cuda_bf16.h>
#include <math_constants.h>
#include <cstdint>
#include <cstddef>

// ---------------------------------------------------------------------------
// Problem constants
// ---------------------------------------------------------------------------
#define BSZ 4
#define SEQ 2048
#define DIM 1024
#define MTOT (BSZ * SEQ)     // 8192
#define K3P (3 * DIM)        // 3072: 3-slot split K for proj/scores/out
#define K3S (3 * SEQ)        // 6144: 3-slot split K for PV

// GEMM modes
#define M_QA  0   // C = A*B^T + bias -> layout-A triples   (q proj, also PV A-out)
#define M_KB  1   // C = A*B^T + bias -> layout-B triples   (k proj)
#define M_VT  2   // C = A*B^T + bias -> layout-B triples, TRANSPOSED (v proj)
#define M_SC  3   // C = |A*B^T| / 32 -> fp32               (scores, causal skip)
#define M_PV  4   // C = A*B (k-limited) -> layout-A triples (P*V)
#define M_OUT 5   // C = A*B^T + bias -> fp32 to d_out      (out proj)

// ---------------------------------------------------------------------------
// Scratch (__device__ globals; allocation-free). "3" = 3-slot split buffers.
// Layout A per k: (hi, hi, lo).  Layout B per k: (hi, lo, hi).
// A-side GEMM over K3 computes hi*hi + hi*lo + lo*hi  (Markidis 3-term).
// ---------------------------------------------------------------------------
__device__ __nv_bfloat16 g_x3[(size_t)MTOT * K3P];            // 50 MB (layout A)
__device__ __nv_bfloat16 g_wq3[DIM * K3P], g_wk3[DIM * K3P];  // layout B
__device__ __nv_bfloat16 g_wv3[DIM * K3P], g_wo3[DIM * K3P];  // layout B
__device__ __nv_bfloat16 g_q3[(size_t)MTOT * K3P];            // layout A
__device__ __nv_bfloat16 g_k3[(size_t)MTOT * K3P];            // layout B
__device__ __nv_bfloat16 g_vt3[(size_t)BSZ * DIM * K3S];      // layout B (V^T)
__device__ float         g_ps[(size_t)BSZ * SEQ * SEQ];       // 64 MB
__device__ __nv_bfloat16 g_p3[(size_t)BSZ * SEQ * K3S];       // 100 MB (layout A)
__device__ __nv_bfloat16 g_o3[(size_t)MTOT * K3P];            // layout A

// ---------------------------------------------------------------------------
// Helpers
// ---------------------------------------------------------------------------
__device__ __forceinline__ uint32_t smem_u32(const void* p) {
    return (uint32_t)__cvta_generic_to_shared(p);
}

__device__ __forceinline__ void split2(float v, __nv_bfloat16& h, __nv_bfloat16& l) {
    h = __float2bfloat16_rn(v);
    l = __float2bfloat16_rn(v - __bfloat162float(h));
}

__device__ __forceinline__ uint32_t pkb(__nv_bfloat16 a, __nv_bfloat16 b) {
    return (uint32_t)__bfloat16_as_ushort(a) |
           ((uint32_t)__bfloat16_as_ushort(b) << 16);   // a at lower address
}

// Write a PAIR of adjacent outputs (cols c, c+1) as 3 uints.
// Layout A: [h0,h0,l0, h1,h1,l1]   Layout B: [h0,l0,h0, h1,l1,h1]
__device__ __forceinline__ void store_tri_a(uint32_t* w, float v0, float v1) {
    __nv_bfloat16 h0, l0, h1, l1;
    split2(v0, h0, l0);
    split2(v1, h1, l1);
    w[0] = pkb(h0, h0);
    w[1] = pkb(l0, h1);
    w[2] = pkb(h1, l1);
}
__device__ __forceinline__ void store_tri_b(uint32_t* w, float v0, float v1) {
    __nv_bfloat16 h0, l0, h1, l1;
    split2(v0, h0, l0);
    split2(v1, h1, l1);
    w[0] = pkb(h0, l0);
    w[1] = pkb(h0, h1);
    w[2] = pkb(l1, h1);
}

// ---------------------------------------------------------------------------
// bf16 HMMA GEMM (NT): D[m][n] = sum_k A[m][k] * B[n][k], fp32 accumulate.
// CTA 128x128, BK=32, 256 threads, warp grid 2(M) x 4(N), warp tile 64x32,
// mma.m16n8k16, ldmatrix, cp.async double buffering.
// ---------------------------------------------------------------------------
#define BK 32
#define LDS 40                 // smem row stride in bf16 (80 B, pad 8)
#define STG (128 * LDS)

template <int MODE>
__global__ void __launch_bounds__(256)
hgemm(const __nv_bfloat16* __restrict__ A, const __nv_bfloat16* __restrict__ B,
      const float* __restrict__ bias, float* __restrict__ dstF,
      __nv_bfloat16* __restrict__ dstB,
      int K3, int lda, int ldb, int ldc,
      size_t sA, size_t sB, size_t sC)
{
    const int rowStart = blockIdx.y * 128;
    const int colStart = blockIdx.x * 128;
    if (MODE == M_SC && colStart > rowStart + 127) return;  // causal tile skip

    const int bz = blockIdx.z;
    A += (size_t)bz * sA;
    B += (size_t)bz * sB;

    __shared__ __nv_bfloat16 As[2 * STG];
    __shared__ __nv_bfloat16 Bs[2 * STG];

    const int tid = threadIdx.x;
    const int lane = tid & 31;
    const int wid = tid >> 5;
    const int wm = wid >> 2;     // 0..1
    const int wn = wid & 3;      // 0..3

    float acc[4][4][4];
    #pragma unroll
    for (int i = 0; i < 4; i++)
        #pragma unroll
        for (int j = 0; j < 4; j++)
            #pragma unroll
            for (int t = 0; t < 4; t++) acc[i][j][t] = 0.0f;

    const int kEnd = (MODE == M_PV) ? 3 * (rowStart + 128) : K3;
    const int nCh = kEnd >> 5;          // kEnd always a multiple of 32 here

    const int ldRow = tid >> 2;         // 0..63
    const int ldC4  = (tid & 3) * 8;    // bf16 offset within 32-wide chunk

    auto load_stage = [&](int c) {
        const int buf = c & 1;
        const int k0 = c << 5;
        #pragma unroll
        for (int i = 0; i < 2; i++) {
            const int r = ldRow + i * 64;
            const uint32_t da = smem_u32(&As[buf * STG + r * LDS + ldC4]);
            const __nv_bfloat16* sa = A + (size_t)(rowStart + r) * lda + k0 + ldC4;
            asm volatile("cp.async.cg.shared.global [%0], [%1], 16;"
                         :: "r"(da), "l"(sa));
            const uint32_t db = smem_u32(&Bs[buf * STG + r * LDS + ldC4]);
            const __nv_bfloat16* sb = B + (size_t)(colStart + r) * ldb + k0 + ldC4;
            asm volatile("cp.async.cg.shared.global [%0], [%1], 16;"
                         :: "r"(db), "l"(sb));
        }
        asm volatile("cp.async.commit_group;");
    };

    load_stage(0);

    for (int c = 0; c < nCh; c++) {
        if (c + 1 < nCh) {
            load_stage(c + 1);
            asm volatile("cp.async.wait_group 1;");
        } else {
            asm volatile("cp.async.wait_group 0;");
        }
        __syncthreads();

        const int buf = c & 1;
        const __nv_bfloat16* as = &As[buf * STG];
        const __nv_bfloat16* bs = &Bs[buf * STG];

        #pragma unroll
        for (int kt = 0; kt < 2; kt++) {
            uint32_t aF[4][4];
            uint32_t bF[4][2];
            {
                const int li = lane >> 3;
                const int lr = lane & 7;
                #pragma unroll
                for (int mt = 0; mt < 4; mt++) {
                    const int row = wm * 64 + mt * 16 + (li & 1) * 8 + lr;
                    const int col = kt * 16 + (li >> 1) * 8;
                    const uint32_t ad = smem_u32(&as[row * LDS + col]);
                    asm volatile(
                        "ldmatrix.sync.aligned.m8n8.x4.shared.b16 "
                        "{%0, %1, %2, %3}, [%4];"
                        : "=r"(aF[mt][0]), "=r"(aF[mt][1]),
                          "=r"(aF[mt][2]), "=r"(aF[mt][3])
                        : "r"(ad));
                }
            }
            {
                const int li = (lane >> 3) & 1;
                const int lr = lane & 7;
                #pragma unroll
                for (int nt = 0; nt < 4; nt++) {
                    const int row = wn * 32 + nt * 8 + lr;
                    const int col = kt * 16 + li * 8;
                    const uint32_t bd = smem_u32(&bs[row * LDS + col]);
                    asm volatile(
                        "ldmatrix.sync.aligned.m8n8.x2.shared.b16 "
                        "{%0, %1}, [%2];"
                        : "=r"(bF[nt][0]), "=r"(bF[nt][1])
                        : "r"(bd));
                }
            }
            #pragma unroll
            for (int mt = 0; mt < 4; mt++)
                #pragma unroll
                for (int nt = 0; nt < 4; nt++) {
                    asm volatile(
                        "mma.sync.aligned.m16n8k16.row.col.f32.bf16.bf16.f32 "
                        "{%0, %1, %2, %3}, {%4, %5, %6, %7}, {%8, %9}, "
                        "{%0, %1, %2, %3};"
                        : "+f"(acc[mt][nt][0]), "+f"(acc[mt][nt][1]),
                          "+f"(acc[mt][nt][2]), "+f"(acc[mt][nt][3])
                        : "r"(aF[mt][0]), "r"(aF[mt][1]),
                          "r"(aF[mt][2]), "r"(aF[mt][3]),
                          "r"(bF[nt][0]), "r"(bF[nt][1]));
                }
        }
        __syncthreads();
    }

    // ---------------- epilogue ----------------
    const int rBase = rowStart + wm * 64 + (lane >> 2);
    const int cBase = colStart + wn * 32 + 2 * (lane & 3);   // always even

    #pragma unroll
    for (int mt = 0; mt < 4; mt++) {
        #pragma unroll
        for (int half = 0; half < 2; half++) {
            const int row = rBase + mt * 16 + half * 8;
            #pragma unroll
            for (int nt = 0; nt < 4; nt++) {
                const int col = cBase + nt * 8;
                float v0 = acc[mt][nt][half * 2 + 0];
                float v1 = acc[mt][nt][half * 2 + 1];

                if (MODE == M_QA || MODE == M_KB || MODE == M_PV) {
                    if (MODE != M_PV) { v0 += bias[col]; v1 += bias[col + 1]; }
                    uint32_t* w = (uint32_t*)(dstB + (size_t)bz * sC +
                                              (size_t)row * ldc + 3 * col);
                    if (MODE == M_KB) store_tri_b(w, v0, v1);
                    else              store_tri_a(w, v0, v1);
                } else if (MODE == M_VT) {
                    // transposed: (row = b*SEQ + s, col = d) -> vt3[b][d][3s..]
                    const int bb = row >> 11, s = row & (SEQ - 1);
                    __nv_bfloat16 h, l;
                    split2(v0 + bias[col], h, l);
                    __nv_bfloat16* q0 = dstB + ((size_t)bb * DIM + col) * K3S + 3 * s;
                    q0[0] = h; q0[1] = l; q0[2] = h;          // layout B
                    split2(v1 + bias[col + 1], h, l);
                    __nv_bfloat16* q1 = dstB + ((size_t)bb * DIM + col + 1) * K3S + 3 * s;
                    q1[0] = h; q1[1] = l; q1[2] = h;
                } else if (MODE == M_SC) {
                    float2 w;
                    w.x = fabsf(v0) * 0.03125f;
                    w.y = fabsf(v1) * 0.03125f;
                    *(float2*)(dstF + (size_t)bz * sC + (size_t)row * ldc + col) = w;
                } else { // M_OUT
                    float2 w;
                    w.x = v0 + bias[col];
                    w.y = v1 + bias[col + 1];
                    *(float2*)(dstF + (size_t)row * ldc + col) = w;
                }
            }
        }
    }
}

// ---------------------------------------------------------------------------
// fp32 -> 3-slot split, layout A (hi,hi,lo) and layout B (hi,lo,hi).
// Processes 2 floats -> 3 uints per thread.
// ---------------------------------------------------------------------------
__global__ void __launch_bounds__(256)
split_f32_a(const float* __restrict__ s, __nv_bfloat16* __restrict__ d, int n2)
{
    const int i = blockIdx.x * 256 + threadIdx.x;
    if (i >= n2) return;
    const float2 v = ((const float2*)s)[i];
    store_tri_a((uint32_t*)(d + (size_t)6 * i), v.x, v.y);
}
__global__ void __launch_bounds__(256)
split_f32_b(const float* __restrict__ s, __nv_bfloat16* __restrict__ d, int n2)
{
    const int i = blockIdx.x * 256 + threadIdx.x;
    if (i >= n2) return;
    const float2 v = ((const float2*)s)[i];
    store_tri_b((uint32_t*)(d + (size_t)6 * i), v.x, v.y);
}

// ---------------------------------------------------------------------------
// Causal softmax: row q uses keys j<=q; writes layout-A triples with zeros
// up to the 128-padded block end (exactly what the PV k-limit reads).
// ---------------------------------------------------------------------------
__global__ void __launch_bounds__(256)
softmax_split(const float* __restrict__ P, __nv_bfloat16* __restrict__ P3)
{
    const int id = blockIdx.x;                 // 0..BSZ*SEQ-1
    const int q = id & (SEQ - 1);
    const float* p = P + (size_t)id * SEQ;
    __nv_bfloat16* p3 = P3 + (size_t)id * K3S;
    const int len = q + 1;
    const int rEnd = ((q >> 7) + 1) << 7;      // multiple of 128
    const int tid = threadIdx.x;

    __shared__ float buf[SEQ];
    __shared__ float red[8];

    float m = -CUDART_INF_F;
    for (int j = tid; j < len; j += 256) {
        const float v = p[j];
        buf[j] = v;
        m = fmaxf(m, v);
    }
    #pragma unroll
    for (int o = 16; o; o >>= 1) m = fmaxf(m, __shfl_xor_sync(0xffffffffu, m, o));
    if ((tid & 31) == 0) red[tid >> 5] = m;
    __syncthreads();
    if (tid == 0) {
        float t = red[0];
        #pragma unroll
        for (int w = 1; w < 8; w++) t = fmaxf(t, red[w]);
        red[0] = t;
    }
    __syncthreads();
    m = red[0];
    __syncthreads();

    float s = 0.0f;
    for (int j = tid; j < len; j += 256) {
        const float e = __expf(buf[j] - m);
        buf[j] = e;
        s += e;
    }
    #pragma unroll
    for (int o = 16; o; o >>= 1) s += __shfl_xor_sync(0xffffffffu, s, o);
    if ((tid & 31) == 0) red[tid >> 5] = s;
    __syncthreads();
    if (tid == 0) {
        float t = 0.0f;
        #pragma unroll
        for (int w = 0; w < 8; w++) t += red[w];
        red[0] = t;
    }
    __syncthreads();
    const float inv = 1.0f / red[0];

    for (int j = 2 * tid; j < rEnd; j += 512) {
        const float v0 = (j     < len) ? buf[j]     * inv : 0.0f;
        const float v1 = (j + 1 < len) ? buf[j + 1] * inv : 0.0f;
        store_tri_a((uint32_t*)(p3 + 3 * j), v0, v1);
    }
}

// ---------------------------------------------------------------------------
extern "C" void kernel_launch(void* const* d_in, const int* in_sizes, int n_in,
                              void* d_out, int out_size)
{
    const float* x  = (const float*)d_in[0];
    const float* Wq = (const float*)d_in[1];
    const float* bq = (const float*)d_in[2];
    const float* Wk = (const float*)d_in[3];
    const float* bk = (const float*)d_in[4];
    const float* Wv = (const float*)d_in[5];
    const float* bv = (const float*)d_in[6];
    const float* Wo = (const float*)d_in[7];
    const float* bo = (const float*)d_in[8];
    float* out = (float*)d_out;

    __nv_bfloat16 *x3, *wq3, *wk3, *wv3, *wo3, *q3, *k3, *vt3, *p3, *o3;
    float* ps;
    cudaGetSymbolAddress((void**)&x3, g_x3);
    cudaGetSymbolAddress((void**)&wq3, g_wq3);
    cudaGetSymbolAddress((void**)&wk3, g_wk3);
    cudaGetSymbolAddress((void**)&wv3, g_wv3);
    cudaGetSymbolAddress((void**)&wo3, g_wo3);
    cudaGetSymbolAddress((void**)&q3, g_q3);
    cudaGetSymbolAddress((void**)&k3, g_k3);
    cudaGetSymbolAddress((void**)&vt3, g_vt3);
    cudaGetSymbolAddress((void**)&ps, g_ps);
    cudaGetSymbolAddress((void**)&p3, g_p3);
    cudaGetSymbolAddress((void**)&o3, g_o3);

    // 0. fp32 -> 3-slot split (x: layout A; weights: layout B)
    split_f32_a<<<MTOT * DIM / 2 / 256, 256>>>(x, x3, MTOT * DIM / 2);
    split_f32_b<<<DIM * DIM / 2 / 256, 256>>>(Wq, wq3, DIM * DIM / 2);
    split_f32_b<<<DIM * DIM / 2 / 256, 256>>>(Wk, wk3, DIM * DIM / 2);
    split_f32_b<<<DIM * DIM / 2 / 256, 256>>>(Wv, wv3, DIM * DIM / 2);
    split_f32_b<<<DIM * DIM / 2 / 256, 256>>>(Wo, wo3, DIM * DIM / 2);

    // 1. projections: [8192,1024] = x * W^T + b
    {
        dim3 g(DIM / 128, MTOT / 128, 1);
        hgemm<M_QA><<<g, 256>>>(x3, wq3, bq, nullptr, q3,
                                K3P, K3P, K3P, K3P, 0, 0, 0);
        hgemm<M_KB><<<g, 256>>>(x3, wk3, bk, nullptr, k3,
                                K3P, K3P, K3P, K3P, 0, 0, 0);
        hgemm<M_VT><<<g, 256>>>(x3, wv3, bv, nullptr, vt3,
                                K3P, K3P, K3P, 0, 0, 0, 0);
    }

    // 2. scores: P = |Q K^T| / 32 (tiles at/below diagonal only)
    {
        dim3 g(SEQ / 128, SEQ / 128, BSZ);
        hgemm<M_SC><<<g, 256>>>(q3, k3, nullptr, ps, nullptr,
                                K3P, K3P, K3P, SEQ,
                                (size_t)SEQ * K3P, (size_t)SEQ * K3P,
                                (size_t)SEQ * SEQ);
    }

    // 3. causal softmax -> layout-A split P
    softmax_split<<<BSZ * SEQ, 256>>>(ps, p3);

    // 4. O = P * V (via transposed layout-B V, causal k-limit)
    {
        dim3 g(DIM / 128, SEQ / 128, BSZ);
        hgemm<M_PV><<<g, 256>>>(p3, vt3, nullptr, nullptr, o3,
                                K3S, K3S, K3S, K3P,
                                (size_t)SEQ * K3S, (size_t)DIM * K3S,
                                (size_t)SEQ * K3P);
    }

    // 5. out = O * Wo^T + bo
    {
        dim3 g(DIM / 128, MTOT / 128, 1);
        hgemm<M_OUT><<<g, 256>>>(o3, wo3, bo, out, nullptr,
                                 K3P, K3P, K3P, DIM, 0, 0, 0);
    }
}

// round 15
// speedup vs baseline: 2.1144x; 1.0288x over previous
#include <cuda_runtime.h>
#include <cuda_bf16.h>
#include <math_constants.h>
#include <cstdint>
#include <cstddef>

// ---------------------------------------------------------------------------
// Problem constants
// ---------------------------------------------------------------------------
#define BSZ 4
#define SEQ 2048
#define DIM 1024
#define MTOT (BSZ * SEQ)     // 8192
#define K3P (3 * DIM)        // 3072
#define K3S (3 * SEQ)        // 6144

// GEMM modes
#define M_QA  0   // C = A*B^T + bias -> layout-A triples   (q proj)
#define M_KB  1   // C = A*B^T + bias -> layout-B triples   (k proj)
#define M_SC  2   // C = |A*B^T| / 32 -> fp32               (scores, causal skip)
#define M_PV  3   // C = A*B (k-limited) -> layout-A triples (P*V)
#define M_OUT 4   // C = A*B^T + bias -> fp32                (v proj / out proj)

// ---------------------------------------------------------------------------
// Scratch. Layout A per k: (hi,hi,lo). Layout B per k: (hi,lo,hi).
// A x B over K3 computes hi*hi + hi*lo + lo*hi (Markidis 3-term).
// ---------------------------------------------------------------------------
__device__ __nv_bfloat16 g_x3[(size_t)MTOT * K3P];
__device__ __nv_bfloat16 g_wq3[DIM * K3P], g_wk3[DIM * K3P];
__device__ __nv_bfloat16 g_wv3[DIM * K3P], g_wo3[DIM * K3P];
__device__ __nv_bfloat16 g_q3[(size_t)MTOT * K3P];            // layout A
__device__ __nv_bfloat16 g_k3[(size_t)MTOT * K3P];            // layout B
__device__ __nv_bfloat16 g_vt3[(size_t)BSZ * DIM * K3S];      // layout B (V^T)
__device__ float         g_ps[(size_t)BSZ * SEQ * SEQ];       // scores; head aliased as V fp32
__device__ __nv_bfloat16 g_p3[(size_t)BSZ * SEQ * K3S];       // layout A
__device__ __nv_bfloat16 g_o3[(size_t)MTOT * K3P];            // layout A

// ---------------------------------------------------------------------------
// Helpers
// ---------------------------------------------------------------------------
__device__ __forceinline__ uint32_t smem_u32(const void* p) {
    return (uint32_t)__cvta_generic_to_shared(p);
}
__device__ __forceinline__ void split2(float v, __nv_bfloat16& h, __nv_bfloat16& l) {
    h = __float2bfloat16_rn(v);
    l = __float2bfloat16_rn(v - __bfloat162float(h));
}
__device__ __forceinline__ uint32_t pkb(__nv_bfloat16 a, __nv_bfloat16 b) {
    return (uint32_t)__bfloat16_as_ushort(a) |
           ((uint32_t)__bfloat16_as_ushort(b) << 16);
}
__device__ __forceinline__ void store_tri_a(uint32_t* w, float v0, float v1) {
    __nv_bfloat16 h0, l0, h1, l1;
    split2(v0, h0, l0);
    split2(v1, h1, l1);
    w[0] = pkb(h0, h0); w[1] = pkb(l0, h1); w[2] = pkb(h1, l1);
}
__device__ __forceinline__ void store_tri_b(uint32_t* w, float v0, float v1) {
    __nv_bfloat16 h0, l0, h1, l1;
    split2(v0, h0, l0);
    split2(v1, h1, l1);
    w[0] = pkb(h0, l0); w[1] = pkb(h0, h1); w[2] = pkb(l1, h1);
}

// ---------------------------------------------------------------------------
// bf16 HMMA GEMM (NT): D[m][n] = sum_k A[m][k]*B[n][k], fp32 accumulate.
// CTA 128x256, 8 warps (warp tile 64x64), BK=32, 3-stage cp.async pipeline.
// ---------------------------------------------------------------------------
#define LDS 40                          // smem row stride (80B, pad)
#define ASTG (128 * LDS)                // elems per A stage
#define BSTG (256 * LDS)                // elems per B stage
#define SMEM_B ((size_t)3 * (ASTG + BSTG) * 2)   // 92160 bytes

template <int MODE>
__global__ void __launch_bounds__(256)
hgemm(const __nv_bfloat16* __restrict__ A, const __nv_bfloat16* __restrict__ B,
      const float* __restrict__ bias, float* __restrict__ dstF,
      __nv_bfloat16* __restrict__ dstB,
      int K3, int lda, int ldb, int ldc,
      size_t sA, size_t sB, size_t sC)
{
    const int rowStart = blockIdx.y * 128;
    const int colStart = blockIdx.x * 256;
    if (MODE == M_SC && colStart > rowStart + 127) return;  // causal tile skip

    const int bz = blockIdx.z;
    A += (size_t)bz * sA;
    B += (size_t)bz * sB;

    extern __shared__ __nv_bfloat16 smem[];
    __nv_bfloat16* As = smem;              // 3 stages
    __nv_bfloat16* Bs = smem + 3 * ASTG;   // 3 stages

    const int tid = threadIdx.x;
    const int lane = tid & 31;
    const int wid = tid >> 5;
    const int wm = wid >> 2;     // 0..1  (M)
    const int wn = wid & 3;      // 0..3  (N)

    float acc[4][8][4];
    #pragma unroll
    for (int i = 0; i < 4; i++)
        #pragma unroll
        for (int j = 0; j < 8; j++)
            #pragma unroll
            for (int t = 0; t < 4; t++) acc[i][j][t] = 0.0f;

    const int kEnd = (MODE == M_PV) ? 3 * (rowStart + 128) : K3;
    const int nCh = kEnd >> 5;

    const int ldRow = tid >> 2;         // 0..63
    const int ldC4  = (tid & 3) * 8;    // bf16 offset within 32-wide chunk

    auto load_stage = [&](int c) {
        const int buf = c % 3;
        const int k0 = c << 5;
        #pragma unroll
        for (int i = 0; i < 2; i++) {
            const int r = ldRow + i * 64;
            const uint32_t da = smem_u32(&As[buf * ASTG + r * LDS + ldC4]);
            const __nv_bfloat16* sa = A + (size_t)(rowStart + r) * lda + k0 + ldC4;
            asm volatile("cp.async.cg.shared.global [%0], [%1], 16;"
                         :: "r"(da), "l"(sa));
        }
        #pragma unroll
        for (int i = 0; i < 4; i++) {
            const int r = ldRow + i * 64;
            const uint32_t db = smem_u32(&Bs[buf * BSTG + r * LDS + ldC4]);
            const __nv_bfloat16* sb = B + (size_t)(colStart + r) * ldb + k0 + ldC4;
            asm volatile("cp.async.cg.shared.global [%0], [%1], 16;"
                         :: "r"(db), "l"(sb));
        }
        asm volatile("cp.async.commit_group;");
    };

    load_stage(0);
    load_stage(1);

    for (int c = 0; c < nCh; c++) {
        asm volatile("cp.async.wait_group 1;");
        __syncthreads();
        if (c + 2 < nCh) load_stage(c + 2);
        else             asm volatile("cp.async.commit_group;");

        const __nv_bfloat16* as = As + (c % 3) * ASTG;
        const __nv_bfloat16* bs = Bs + (c % 3) * BSTG;

        #pragma unroll
        for (int kt = 0; kt < 2; kt++) {
            uint32_t aF[4][4];
            {
                const int li = lane >> 3;
                const int lr = lane & 7;
                #pragma unroll
                for (int mt = 0; mt < 4; mt++) {
                    const int row = wm * 64 + mt * 16 + (li & 1) * 8 + lr;
                    const int col = kt * 16 + (li >> 1) * 8;
                    const uint32_t ad = smem_u32(&as[row * LDS + col]);
                    asm volatile(
                        "ldmatrix.sync.aligned.m8n8.x4.shared.b16 "
                        "{%0, %1, %2, %3}, [%4];"
                        : "=r"(aF[mt][0]), "=r"(aF[mt][1]),
                          "=r"(aF[mt][2]), "=r"(aF[mt][3])
                        : "r"(ad));
                }
            }
            uint32_t bF[8][2];
            {
                const int li = lane >> 3;
                const int lr = lane & 7;
                #pragma unroll
                for (int ntp = 0; ntp < 4; ntp++) {
                    const int row = wn * 64 + ntp * 16 + (li >> 1) * 8 + lr;
                    const int col = kt * 16 + (li & 1) * 8;
                    const uint32_t bd = smem_u32(&bs[row * LDS + col]);
                    uint32_t r0, r1, r2, r3;
                    asm volatile(
                        "ldmatrix.sync.aligned.m8n8.x4.shared.b16 "
                        "{%0, %1, %2, %3}, [%4];"
                        : "=r"(r0), "=r"(r1), "=r"(r2), "=r"(r3)
                        : "r"(bd));
                    bF[2 * ntp][0] = r0;  bF[2 * ntp][1] = r1;
                    bF[2 * ntp + 1][0] = r2;  bF[2 * ntp + 1][1] = r3;
                }
            }
            #pragma unroll
            for (int mt = 0; mt < 4; mt++)
                #pragma unroll
                for (int nt = 0; nt < 8; nt++) {
                    asm volatile(
                        "mma.sync.aligned.m16n8k16.row.col.f32.bf16.bf16.f32 "
                        "{%0, %1, %2, %3}, {%4, %5, %6, %7}, {%8, %9}, "
                        "{%0, %1, %2, %3};"
                        : "+f"(acc[mt][nt][0]), "+f"(acc[mt][nt][1]),
                          "+f"(acc[mt][nt][2]), "+f"(acc[mt][nt][3])
                        : "r"(aF[mt][0]), "r"(aF[mt][1]),
                          "r"(aF[mt][2]), "r"(aF[mt][3]),
                          "r"(bF[nt][0]), "r"(bF[nt][1]));
                }
        }
        __syncthreads();
    }

    // ---------------- epilogue ----------------
    const int rBase = rowStart + wm * 64 + (lane >> 2);
    const int cBase = colStart + wn * 64 + 2 * (lane & 3);   // even

    #pragma unroll
    for (int mt = 0; mt < 4; mt++) {
        #pragma unroll
        for (int half = 0; half < 2; half++) {
            const int row = rBase + mt * 16 + half * 8;
            #pragma unroll
            for (int nt = 0; nt < 8; nt++) {
                const int col = cBase + nt * 8;
                float v0 = acc[mt][nt][half * 2 + 0];
                float v1 = acc[mt][nt][half * 2 + 1];

                if (MODE == M_QA || MODE == M_KB || MODE == M_PV) {
                    if (MODE != M_PV) { v0 += bias[col]; v1 += bias[col + 1]; }
                    uint32_t* w = (uint32_t*)(dstB + (size_t)bz * sC +
                                              (size_t)row * ldc + 3 * col);
                    if (MODE == M_KB) store_tri_b(w, v0, v1);
                    else              store_tri_a(w, v0, v1);
                } else if (MODE == M_SC) {
                    float2 w;
                    w.x = fabsf(v0) * 0.03125f;
                    w.y = fabsf(v1) * 0.03125f;
                    *(float2*)(dstF + (size_t)bz * sC + (size_t)row * ldc + col) = w;
                } else { // M_OUT (also V projection)
                    float2 w;
                    w.x = v0 + bias[col];
                    w.y = v1 + bias[col + 1];
                    *(float2*)(dstF + (size_t)row * ldc + col) = w;
                }
            }
        }
    }
}

// ---------------------------------------------------------------------------
// Transpose + split V: v[b][s][d] fp32 -> vt3[b][d][3s] layout-B triples.
// 32x32 smem tiles; coalesced both sides.
// ---------------------------------------------------------------------------
__global__ void __launch_bounds__(256)
transpose_split_v(const float* __restrict__ v, __nv_bfloat16* __restrict__ vt3)
{
    __shared__ float t[32][33];
    const int s0 = blockIdx.x * 32;
    const int d0 = blockIdx.y * 32;
    const int b  = blockIdx.z;
    const float* vb = v + (size_t)b * SEQ * DIM;

    const int tx = threadIdx.x & 31;
    const int ty = threadIdx.x >> 5;           // 0..7
    #pragma unroll
    for (int i = 0; i < 4; i++) {
        const int s = ty + i * 8;
        t[s][tx] = vb[(size_t)(s0 + s) * DIM + d0 + tx];
    }
    __syncthreads();

    const int d  = threadIdx.x >> 3;           // 0..31
    const int sg = threadIdx.x & 7;            // 0..7 (4 s each)
    __nv_bfloat16* dst = vt3 + ((size_t)b * DIM + d0 + d) * K3S + 3 * (s0 + sg * 4);
    uint32_t wbuf[6];
    uint16_t hv[12];
    #pragma unroll
    for (int j = 0; j < 4; j++) {
        __nv_bfloat16 h, l;
        split2(t[sg * 4 + j][d], h, l);
        hv[3 * j + 0] = __bfloat16_as_ushort(h);   // layout B: h, l, h
        hv[3 * j + 1] = __bfloat16_as_ushort(l);
        hv[3 * j + 2] = __bfloat16_as_ushort(h);
    }
    #pragma unroll
    for (int j = 0; j < 6; j++)
        wbuf[j] = (uint32_t)hv[2 * j] | ((uint32_t)hv[2 * j + 1] << 16);
    uint2* d2 = (uint2*)dst;
    d2[0] = make_uint2(wbuf[0], wbuf[1]);
    d2[1] = make_uint2(wbuf[2], wbuf[3]);
    d2[2] = make_uint2(wbuf[4], wbuf[5]);
}

// ---------------------------------------------------------------------------
// fp32 -> 3-slot split (layouts A and B)
// ---------------------------------------------------------------------------
__global__ void __launch_bounds__(256)
split_f32_a(const float* __restrict__ s, __nv_bfloat16* __restrict__ d, int n2)
{
    const int i = blockIdx.x * 256 + threadIdx.x;
    if (i >= n2) return;
    const float2 v = ((const float2*)s)[i];
    store_tri_a((uint32_t*)(d + (size_t)6 * i), v.x, v.y);
}
__global__ void __launch_bounds__(256)
split_f32_b(const float* __restrict__ s, __nv_bfloat16* __restrict__ d, int n2)
{
    const int i = blockIdx.x * 256 + threadIdx.x;
    if (i >= n2) return;
    const float2 v = ((const float2*)s)[i];
    store_tri_b((uint32_t*)(d + (size_t)6 * i), v.x, v.y);
}

// ---------------------------------------------------------------------------
// Causal softmax -> layout-A triples, zero-padded to 128-block end.
// ---------------------------------------------------------------------------
__global__ void __launch_bounds__(256)
softmax_split(const float* __restrict__ P, __nv_bfloat16* __restrict__ P3)
{
    const int id = blockIdx.x;
    const int q = id & (SEQ - 1);
    const float* p = P + (size_t)id * SEQ;
    __nv_bfloat16* p3 = P3 + (size_t)id * K3S;
    const int len = q + 1;
    const int rEnd = ((q >> 7) + 1) << 7;
    const int tid = threadIdx.x;

    __shared__ float buf[SEQ];
    __shared__ float red[8];

    float m = -CUDART_INF_F;
    for (int j = tid; j < len; j += 256) {
        const float v = p[j];
        buf[j] = v;
        m = fmaxf(m, v);
    }
    #pragma unroll
    for (int o = 16; o; o >>= 1) m = fmaxf(m, __shfl_xor_sync(0xffffffffu, m, o));
    if ((tid & 31) == 0) red[tid >> 5] = m;
    __syncthreads();
    if (tid == 0) {
        float t = red[0];
        #pragma unroll
        for (int w = 1; w < 8; w++) t = fmaxf(t, red[w]);
        red[0] = t;
    }
    __syncthreads();
    m = red[0];
    __syncthreads();

    float s = 0.0f;
    for (int j = tid; j < len; j += 256) {
        const float e = __expf(buf[j] - m);
        buf[j] = e;
        s += e;
    }
    #pragma unroll
    for (int o = 16; o; o >>= 1) s += __shfl_xor_sync(0xffffffffu, s, o);
    if ((tid & 31) == 0) red[tid >> 5] = s;
    __syncthreads();
    if (tid == 0) {
        float t = 0.0f;
        #pragma unroll
        for (int w = 0; w < 8; w++) t += red[w];
        red[0] = t;
    }
    __syncthreads();
    const float inv = 1.0f / red[0];

    for (int j = 2 * tid; j < rEnd; j += 512) {
        const float v0 = (j     < len) ? buf[j]     * inv : 0.0f;
        const float v1 = (j + 1 < len) ? buf[j + 1] * inv : 0.0f;
        store_tri_a((uint32_t*)(p3 + 3 * j), v0, v1);
    }
}

// ---------------------------------------------------------------------------
extern "C" void kernel_launch(void* const* d_in, const int* in_sizes, int n_in,
                              void* d_out, int out_size)
{
    const float* x  = (const float*)d_in[0];
    const float* Wq = (const float*)d_in[1];
    const float* bq = (const float*)d_in[2];
    const float* Wk = (const float*)d_in[3];
    const float* bk = (const float*)d_in[4];
    const float* Wv = (const float*)d_in[5];
    const float* bv = (const float*)d_in[6];
    const float* Wo = (const float*)d_in[7];
    const float* bo = (const float*)d_in[8];
    float* out = (float*)d_out;

    __nv_bfloat16 *x3, *wq3, *wk3, *wv3, *wo3, *q3, *k3, *vt3, *p3, *o3;
    float* ps;
    cudaGetSymbolAddress((void**)&x3, g_x3);
    cudaGetSymbolAddress((void**)&wq3, g_wq3);
    cudaGetSymbolAddress((void**)&wk3, g_wk3);
    cudaGetSymbolAddress((void**)&wv3, g_wv3);
    cudaGetSymbolAddress((void**)&wo3, g_wo3);
    cudaGetSymbolAddress((void**)&q3, g_q3);
    cudaGetSymbolAddress((void**)&k3, g_k3);
    cudaGetSymbolAddress((void**)&vt3, g_vt3);
    cudaGetSymbolAddress((void**)&ps, g_ps);
    cudaGetSymbolAddress((void**)&p3, g_p3);
    cudaGetSymbolAddress((void**)&o3, g_o3);
    float* vbuf = ps;   // alias: V fp32 lives in ps until scores overwrite it

    cudaFuncSetAttribute(hgemm<M_QA>,  cudaFuncAttributeMaxDynamicSharedMemorySize, (int)SMEM_B);
    cudaFuncSetAttribute(hgemm<M_KB>,  cudaFuncAttributeMaxDynamicSharedMemorySize, (int)SMEM_B);
    cudaFuncSetAttribute(hgemm<M_SC>,  cudaFuncAttributeMaxDynamicSharedMemorySize, (int)SMEM_B);
    cudaFuncSetAttribute(hgemm<M_PV>,  cudaFuncAttributeMaxDynamicSharedMemorySize, (int)SMEM_B);
    cudaFuncSetAttribute(hgemm<M_OUT>, cudaFuncAttributeMaxDynamicSharedMemorySize, (int)SMEM_B);

    // 0. fp32 -> 3-slot split
    split_f32_a<<<MTOT * DIM / 2 / 256, 256>>>(x, x3, MTOT * DIM / 2);
    split_f32_b<<<DIM * DIM / 2 / 256, 256>>>(Wq, wq3, DIM * DIM / 2);
    split_f32_b<<<DIM * DIM / 2 / 256, 256>>>(Wk, wk3, DIM * DIM / 2);
    split_f32_b<<<DIM * DIM / 2 / 256, 256>>>(Wv, wv3, DIM * DIM / 2);
    split_f32_b<<<DIM * DIM / 2 / 256, 256>>>(Wo, wo3, DIM * DIM / 2);

    // 1. projections
    {
        dim3 g(DIM / 256, MTOT / 128, 1);
        hgemm<M_QA><<<g, 256, SMEM_B>>>(x3, wq3, bq, nullptr, q3,
                                        K3P, K3P, K3P, K3P, 0, 0, 0);
        hgemm<M_KB><<<g, 256, SMEM_B>>>(x3, wk3, bk, nullptr, k3,
                                        K3P, K3P, K3P, K3P, 0, 0, 0);
        hgemm<M_OUT><<<g, 256, SMEM_B>>>(x3, wv3, bv, vbuf, nullptr,
                                         K3P, K3P, K3P, DIM, 0, 0, 0);
    }

    // 1b. V fp32 -> transposed layout-B triples
    {
        dim3 g(SEQ / 32, DIM / 32, BSZ);
        transpose_split_v<<<g, 256>>>(vbuf, vt3);
    }

    // 2. scores: |Q K^T| / 32 (tiles at/below diagonal only); overwrites ps
    {
        dim3 g(SEQ / 256, SEQ / 128, BSZ);
        hgemm<M_SC><<<g, 256, SMEM_B>>>(q3, k3, nullptr, ps, nullptr,
                                        K3P, K3P, K3P, SEQ,
                                        (size_t)SEQ * K3P, (size_t)SEQ * K3P,
                                        (size_t)SEQ * SEQ);
    }

    // 3. causal softmax -> layout-A P triples
    softmax_split<<<BSZ * SEQ, 256>>>(ps, p3);

    // 4. O = P * V (k-limited)
    {
        dim3 g(DIM / 256, SEQ / 128, BSZ);
        hgemm<M_PV><<<g, 256, SMEM_B>>>(p3, vt3, nullptr, nullptr, o3,
                                        K3S, K3S, K3S, K3P,
                                        (size_t)SEQ * K3S, (size_t)DIM * K3S,
                                        (size_t)SEQ * K3P);
    }

    // 5. out = O * Wo^T + bo
    {
        dim3 g(DIM / 256, MTOT / 128, 1);
        hgemm<M_OUT><<<g, 256, SMEM_B>>>(o3, wo3, bo, out, nullptr,
                                         K3P, K3P, K3P, DIM, 0, 0, 0);
    }
}